// round 4
// baseline (speedup 1.0000x reference)
#include <cuda_runtime.h>
#include <math.h>

#define BB   16
#define CC   512
#define HWD  4096
#define BIG  (BB*CC*HWD)
#define EPSV 1e-8f
#define KTOP 12

// ---------------- scratch ----------------------------------------------------
__device__ float    g_pred[BB*HWD];
__device__ float    g_mf[BB*HWD];         // fg mask 0/1
__device__ float    g_mb[BB*HWD];         // bg mask 0/1
__device__ int      g_pcnt[2*BB*16];      // per-block counts from k_sim
__device__ float    g_fgsum[BB*CC];
__device__ float    g_bgsum[BB*CC];
__device__ float    g_proto[2*BB*CC];
__device__ float    g_pnorm[2*BB];
__device__ float    g_act[BB*HWD];
__device__ float    g_deact[BB*HWD];
__device__ unsigned g_mm[4];              // amin,amax,dmin,dmax ordered-uint

// ---------------- helpers ----------------------------------------------------
__device__ __forceinline__ unsigned fenc(float f) {
    unsigned u = __float_as_uint(f);
    return (u & 0x80000000u) ? ~u : (u | 0x80000000u);
}
__device__ __forceinline__ float fdec(unsigned e) {
    return (e & 0x80000000u) ? __uint_as_float(e & 0x7fffffffu)
                             : __uint_as_float(~e);
}

__device__ __forceinline__ float blkSum(float v, float* sh) {
    int lane = threadIdx.x & 31, w = threadIdx.x >> 5;
#pragma unroll
    for (int o = 16; o; o >>= 1) v += __shfl_down_sync(0xffffffffu, v, o);
    if (lane == 0) sh[w] = v;
    __syncthreads();
    if (w == 0) {
        float r = (lane < 8) ? sh[lane] : 0.f;
#pragma unroll
        for (int o = 4; o; o >>= 1) r += __shfl_down_sync(0xffffffffu, r, o);
        if (lane == 0) sh[0] = r;
    }
    __syncthreads();
    float r = sh[0];
    __syncthreads();
    return r;
}

__device__ __forceinline__ unsigned blkUMin(unsigned v, unsigned* sh) {
    int lane = threadIdx.x & 31, w = threadIdx.x >> 5;
#pragma unroll
    for (int o = 16; o; o >>= 1) v = min(v, __shfl_down_sync(0xffffffffu, v, o));
    if (lane == 0) sh[w] = v;
    __syncthreads();
    if (w == 0) {
        unsigned r = (lane < 8) ? sh[lane] : 0xFFFFFFFFu;
#pragma unroll
        for (int o = 4; o; o >>= 1) r = min(r, __shfl_down_sync(0xffffffffu, r, o));
        if (lane == 0) sh[0] = r;
    }
    __syncthreads();
    unsigned r = sh[0];
    __syncthreads();
    return r;
}
__device__ __forceinline__ unsigned blkUMax(unsigned v, unsigned* sh) {
    int lane = threadIdx.x & 31, w = threadIdx.x >> 5;
#pragma unroll
    for (int o = 16; o; o >>= 1) v = max(v, __shfl_down_sync(0xffffffffu, v, o));
    if (lane == 0) sh[w] = v;
    __syncthreads();
    if (w == 0) {
        unsigned r = (lane < 8) ? sh[lane] : 0u;
#pragma unroll
        for (int o = 4; o; o >>= 1) r = max(r, __shfl_down_sync(0xffffffffu, r, o));
        if (lane == 0) sh[0] = r;
    }
    __syncthreads();
    unsigned r = sh[0];
    __syncthreads();
    return r;
}

// ---------------- kernel 1: pred + masks + counts (pixel-major) --------------
__global__ __launch_bounds__(256)
void k_sim(const float* __restrict__ feat, const float* __restrict__ sfp,
           const float* __restrict__ sbp, const float* __restrict__ tau) {
    __shared__ float s_fp[CC], s_bp[CC];
    __shared__ float sh[32];
    __shared__ int   shc[2][8];
    int b = blockIdx.x >> 4, chunk = blockIdx.x & 15;
    int tid = threadIdx.x;

    if (blockIdx.x == 0 && tid < 4)
        g_mm[tid] = (tid & 1) ? 0u : 0xFFFFFFFFu;

    float nf = 0.f, nb = 0.f;
    for (int c = tid; c < CC; c += 256) {
        float a = sfp[b*CC + c], d = sbp[b*CC + c];
        s_fp[c] = a; s_bp[c] = d;
        nf += a*a; nb += d*d;
    }
    __syncthreads();
    nf = blkSum(nf, sh);
    nb = blkSum(nb, sh);
    float nfp = sqrtf(nf), nbp = sqrtf(nb);
    float ft  = 1.f / (1.f + expf(-tau[0]));
    float bt  = 1.f - ft;

    int p = (chunk << 8) + tid;
    const float* fb = feat + (size_t)b*CC*HWD + p;
    float dfg = 0.f, dbg = 0.f, nq = 0.f;
#pragma unroll 32
    for (int c = 0; c < CC; c++) {
        float x = __ldg(&fb[(size_t)c*HWD]);
        dfg = fmaf(x, s_fp[c], dfg);
        dbg = fmaf(x, s_bp[c], dbg);
        nq  = fmaf(x, x, nq);
    }
    float inv_q = 1.f / fmaxf(sqrtf(nq), EPSV);
    float cfg = dfg * inv_q / fmaxf(nfp, EPSV);
    float cbg = dbg * inv_q / fmaxf(nbp, EPSV);
    float pf  = 1.f / (1.f + expf(10.f * (cbg - cfg)));
    float pb  = 1.f / (1.f + expf(10.f * (cfg - cbg)));
    bool mfb = pf > ft;
    bool mbb = pb > bt;
    int gp = b*HWD + p;
    g_pred[gp] = pf;
    g_mf[gp] = mfb ? 1.f : 0.f;
    g_mb[gp] = mbb ? 1.f : 0.f;

    unsigned bf  = __ballot_sync(0xffffffffu, mfb);
    unsigned bbt = __ballot_sync(0xffffffffu, mbb);
    int w = tid >> 5;
    if ((tid & 31) == 0) { shc[0][w] = __popc(bf); shc[1][w] = __popc(bbt); }
    __syncthreads();
    if (tid == 0) {
        int cf = 0, cb = 0;
#pragma unroll
        for (int j = 0; j < 8; j++) { cf += shc[0][j]; cb += shc[1][j]; }
        g_pcnt[blockIdx.x]            = cf;
        g_pcnt[BB*16 + blockIdx.x]    = cb;
    }
}

// ---------------- kernel 2: masked channel sums (channel-major, float4) ------
__global__ __launch_bounds__(256)
void k_msum(const float* __restrict__ feat) {
    __shared__ float4 s_mf4[HWD/4];   // 16 KB
    __shared__ float4 s_mb4[HWD/4];   // 16 KB
    int b = blockIdx.x >> 4, cg = blockIdx.x & 15;
    int tid = threadIdx.x, w = tid >> 5, l = tid & 31;

    const float4* mf4 = (const float4*)(g_mf + b*HWD);
    const float4* mb4 = (const float4*)(g_mb + b*HWD);
#pragma unroll
    for (int k = 0; k < 4; k++) {
        s_mf4[tid + k*256] = mf4[tid + k*256];
        s_mb4[tid + k*256] = mb4[tid + k*256];
    }
    __syncthreads();

#pragma unroll
    for (int k = 0; k < 4; k++) {
        int c = (cg << 5) + (w << 2) + k;
        const float4* row = (const float4*)(feat + ((size_t)(b*CC + c))*HWD);
        float sf = 0.f, sb = 0.f;
#pragma unroll 8
        for (int i = 0; i < 32; i++) {
            float4 x = __ldg(&row[l + (i << 5)]);
            float4 mfv = s_mf4[l + (i << 5)];
            float4 mbv = s_mb4[l + (i << 5)];
            sf = fmaf(x.x, mfv.x, sf); sf = fmaf(x.y, mfv.y, sf);
            sf = fmaf(x.z, mfv.z, sf); sf = fmaf(x.w, mfv.w, sf);
            sb = fmaf(x.x, mbv.x, sb); sb = fmaf(x.y, mbv.y, sb);
            sb = fmaf(x.z, mbv.z, sb); sb = fmaf(x.w, mbv.w, sb);
        }
#pragma unroll
        for (int o = 16; o; o >>= 1) {
            sf += __shfl_down_sync(0xffffffffu, sf, o);
            sb += __shfl_down_sync(0xffffffffu, sb, o);
        }
        if (l == 0) {
            g_fgsum[b*CC + c] = sf;
            g_bgsum[b*CC + c] = sb;
        }
    }
}

// ---------------- kernel 3: prototypes ---------------------------------------
__global__ __launch_bounds__(256)
void k_proto(const float* __restrict__ feat, float* __restrict__ outp) {
    __shared__ float sv[HWD];
    __shared__ int   sel[KTOP];
    __shared__ float shf[32];
    __shared__ float rv[8];
    __shared__ int   ri[8];
    __shared__ int   scnt[16];
    int b = blockIdx.x >> 1, cls = blockIdx.x & 1;
    int tid = threadIdx.x;

    if (tid < 16) scnt[tid] = g_pcnt[cls*BB*16 + b*16 + tid];
    __syncthreads();
    if (tid == 0) {
        int s = 0;
#pragma unroll
        for (int j = 0; j < 16; j++) s += scnt[j];
        scnt[0] = s;
    }
    __syncthreads();
    int cnt = scnt[0];

    if (cnt == 0) {   // stable top-12 fallback
        for (int p = tid; p < HWD; p += 256) {
            float pf = g_pred[b*HWD + p];
            sv[p] = cls ? (1.f - pf) : pf;
        }
        __syncthreads();
        for (int r = 0; r < KTOP; r++) {
            float bv = -1e30f; int bi = HWD;
            for (int p = tid; p < HWD; p += 256) {
                float v = sv[p];
                if (v > bv) { bv = v; bi = p; }
            }
            int lane = tid & 31, w = tid >> 5;
#pragma unroll
            for (int o = 16; o; o >>= 1) {
                float ov = __shfl_down_sync(0xffffffffu, bv, o);
                int   oi = __shfl_down_sync(0xffffffffu, bi, o);
                if (ov > bv || (ov == bv && oi < bi)) { bv = ov; bi = oi; }
            }
            if (lane == 0) { rv[w] = bv; ri[w] = bi; }
            __syncthreads();
            if (tid == 0) {
                for (int j = 1; j < 8; j++)
                    if (rv[j] > bv || (rv[j] == bv && ri[j] < bi)) { bv = rv[j]; bi = ri[j]; }
                sel[r] = bi;
                sv[bi] = -1e30f;
            }
            __syncthreads();
        }
    }
    __syncthreads();

    float inv = (cnt > 0) ? 1.f / (float)cnt : (1.f / (float)KTOP);
    const float* sums = cls ? g_bgsum : g_fgsum;
    float n2 = 0.f;
    for (int c = tid; c < CC; c += 256) {
        float v;
        if (cnt > 0) {
            v = sums[b*CC + c] * inv;
        } else {
            float s = 0.f;
#pragma unroll
            for (int j = 0; j < KTOP; j++)
                s += feat[((size_t)(b*CC + c))*HWD + sel[j]];
            v = s * inv;
        }
        g_proto[(cls*BB + b)*CC + c] = v;
        outp[BIG + cls*BB*CC + b*CC + c] = v;
        n2 += v*v;
    }
    n2 = blkSum(n2, shf);
    if (tid == 0) g_pnorm[cls*BB + b] = sqrtf(n2);
}

// ---------------- kernel 4: act/deact + global minmax ------------------------
__global__ __launch_bounds__(256)
void k_act(const float* __restrict__ feat) {
    __shared__ float s_fp[CC], s_bp[CC];
    __shared__ unsigned shu[32];
    int b = blockIdx.x >> 4, chunk = blockIdx.x & 15;
    for (int c = threadIdx.x; c < CC; c += 256) {
        s_fp[c] = g_proto[b*CC + c];
        s_bp[c] = g_proto[(BB + b)*CC + c];
    }
    __syncthreads();
    float nfp = g_pnorm[b], nbp = g_pnorm[BB + b];

    int p = (chunk << 8) + threadIdx.x;
    const float* fb = feat + (size_t)b*CC*HWD + p;
    float dfg = 0.f, dbg = 0.f, nq = 0.f;
#pragma unroll 32
    for (int c = 0; c < CC; c++) {
        float x = __ldg(&fb[(size_t)c*HWD]);
        dfg = fmaf(x, s_fp[c], dfg);
        dbg = fmaf(x, s_bp[c], dbg);
        nq  = fmaf(x, x, nq);
    }
    float inv_q = 1.f / fmaxf(sqrtf(nq), EPSV);
    float ca = dfg * inv_q / fmaxf(nfp, EPSV);
    float cd = dbg * inv_q / fmaxf(nbp, EPSV);
    g_act[b*HWD + p]   = ca;
    g_deact[b*HWD + p] = cd;

    unsigned amn = blkUMin(fenc(ca), shu);
    unsigned amx = blkUMax(fenc(ca), shu);
    unsigned dmn = blkUMin(fenc(cd), shu);
    unsigned dmx = blkUMax(fenc(cd), shu);
    if (threadIdx.x == 0) {
        atomicMin(&g_mm[0], amn);
        atomicMax(&g_mm[1], amx);
        atomicMin(&g_mm[2], dmn);
        atomicMax(&g_mm[3], dmx);
    }
}

// ---------------- kernel 5: blend output -------------------------------------
__global__ __launch_bounds__(256)
void k_out(const float* __restrict__ feat, float* __restrict__ outp) {
    __shared__ float mm[4];
    if (threadIdx.x < 4) mm[threadIdx.x] = fdec(g_mm[threadIdx.x]);
    __syncthreads();
    float amin = mm[0], ira = 1.f / (mm[1] - mm[0]);
    float dmin = mm[2], ird = 1.f / (mm[3] - mm[2]);

    size_t i4 = (size_t)blockIdx.x * 256 + threadIdx.x;
    size_t e  = i4 << 2;
    int b = (int)(e >> 21);            // C*HW = 2^21
    int p = (int)(e & (HWD - 1));
    float4 x = __ldg(&((const float4*)feat)[i4]);
    int ai = (b*HWD + p) >> 2;
    float4 a = ((const float4*)g_act)[ai];
    float4 d = ((const float4*)g_deact)[ai];
    float4 o;
    o.x = x.x * ((a.x - amin)*ira + 1.f - (d.x - dmin)*ird);
    o.y = x.y * ((a.y - amin)*ira + 1.f - (d.y - dmin)*ird);
    o.z = x.z * ((a.z - amin)*ira + 1.f - (d.z - dmin)*ird);
    o.w = x.w * ((a.w - amin)*ira + 1.f - (d.w - dmin)*ird);
    ((float4*)outp)[i4] = o;
}

// ---------------- launch -----------------------------------------------------
extern "C" void kernel_launch(void* const* d_in, const int* in_sizes, int n_in,
                              void* d_out, int out_size) {
    const float* sfp  = (const float*)d_in[0];
    const float* sbp  = (const float*)d_in[1];
    const float* feat = (const float*)d_in[2];
    const float* tau  = (const float*)d_in[3];
    float* outp = (float*)d_out;

    k_sim  <<<BB*16, 256>>>(feat, sfp, sbp, tau);
    k_msum <<<BB*16, 256>>>(feat);
    k_proto<<<2*BB, 256>>>(feat, outp);
    k_act  <<<BB*16, 256>>>(feat);
    k_out  <<<BIG/4/256, 256>>>(feat, outp);
    (void)in_sizes; (void)n_in; (void)out_size;
}

// round 5
// speedup vs baseline: 2.0462x; 2.0462x over previous
#include <cuda_runtime.h>
#include <math.h>

#define BB   16
#define CC   512
#define HWD  4096
#define BIG  (BB*CC*HWD)
#define EPSV 1e-8f
#define KTOP 12
#define SPLIT 4
#define CPS  (CC/SPLIT)          /* 128 channels per split */

// ---------------- scratch ----------------------------------------------------
__device__ float    g_p0[SPLIT*BB*HWD];   // partial dfg (1 MB each)
__device__ float    g_p1[SPLIT*BB*HWD];   // partial dbg
__device__ float    g_p2[SPLIT*BB*HWD];   // partial nq (sim only)
__device__ float    g_pred[BB*HWD];
__device__ float    g_invq[BB*HWD];
__device__ float    g_mf[BB*HWD];
__device__ float    g_mb[BB*HWD];
__device__ int      g_cnt[2*BB];
__device__ float    g_fgsum[BB*CC];
__device__ float    g_bgsum[BB*CC];
__device__ float    g_proto[2*BB*CC];
__device__ float    g_pnorm[2*BB];
__device__ float    g_act[BB*HWD];
__device__ float    g_deact[BB*HWD];
__device__ unsigned g_mm[4];

// ---------------- helpers ----------------------------------------------------
__device__ __forceinline__ unsigned fenc(float f) {
    unsigned u = __float_as_uint(f);
    return (u & 0x80000000u) ? ~u : (u | 0x80000000u);
}
__device__ __forceinline__ float fdec(unsigned e) {
    return (e & 0x80000000u) ? __uint_as_float(e & 0x7fffffffu)
                             : __uint_as_float(~e);
}

__device__ __forceinline__ float blkSum(float v, float* sh) {
    int lane = threadIdx.x & 31, w = threadIdx.x >> 5;
#pragma unroll
    for (int o = 16; o; o >>= 1) v += __shfl_down_sync(0xffffffffu, v, o);
    if (lane == 0) sh[w] = v;
    __syncthreads();
    if (w == 0) {
        float r = (lane < 8) ? sh[lane] : 0.f;
#pragma unroll
        for (int o = 4; o; o >>= 1) r += __shfl_down_sync(0xffffffffu, r, o);
        if (lane == 0) sh[0] = r;
    }
    __syncthreads();
    float r = sh[0];
    __syncthreads();
    return r;
}

__device__ __forceinline__ unsigned blkUMin(unsigned v, unsigned* sh) {
    int lane = threadIdx.x & 31, w = threadIdx.x >> 5;
#pragma unroll
    for (int o = 16; o; o >>= 1) v = min(v, __shfl_down_sync(0xffffffffu, v, o));
    if (lane == 0) sh[w] = v;
    __syncthreads();
    if (w == 0) {
        unsigned r = (lane < 8) ? sh[lane] : 0xFFFFFFFFu;
#pragma unroll
        for (int o = 4; o; o >>= 1) r = min(r, __shfl_down_sync(0xffffffffu, r, o));
        if (lane == 0) sh[0] = r;
    }
    __syncthreads();
    unsigned r = sh[0];
    __syncthreads();
    return r;
}
__device__ __forceinline__ unsigned blkUMax(unsigned v, unsigned* sh) {
    int lane = threadIdx.x & 31, w = threadIdx.x >> 5;
#pragma unroll
    for (int o = 16; o; o >>= 1) v = max(v, __shfl_down_sync(0xffffffffu, v, o));
    if (lane == 0) sh[w] = v;
    __syncthreads();
    if (w == 0) {
        unsigned r = (lane < 8) ? sh[lane] : 0u;
#pragma unroll
        for (int o = 4; o; o >>= 1) r = max(r, __shfl_down_sync(0xffffffffu, r, o));
        if (lane == 0) sh[0] = r;
    }
    __syncthreads();
    unsigned r = sh[0];
    __syncthreads();
    return r;
}

// ------------ k1: partial dots vs support protos (split-C, grid 1024) --------
__global__ __launch_bounds__(256)
void k_sim_part(const float* __restrict__ feat, const float* __restrict__ sfp,
                const float* __restrict__ sbp) {
    __shared__ float s_f[CPS], s_b[CPS];
    int b = blockIdx.x >> 6, rest = blockIdx.x & 63;
    int s = rest >> 4, chunk = rest & 15;
    int tid = threadIdx.x;

    if (blockIdx.x == 0) {
        if (tid < 2*BB) g_cnt[tid] = 0;
        if (tid < 4)    g_mm[tid] = (tid & 1) ? 0u : 0xFFFFFFFFu;
    }
    if (tid < CPS) {
        s_f[tid] = sfp[b*CC + s*CPS + tid];
        s_b[tid] = sbp[b*CC + s*CPS + tid];
    }
    __syncthreads();

    int p = (chunk << 8) + tid;
    const float* fb = feat + ((size_t)(b*CC + s*CPS))*HWD + p;
    float dfg = 0.f, dbg = 0.f, nq = 0.f;
#pragma unroll 16
    for (int c = 0; c < CPS; c++) {
        float x = __ldg(&fb[(size_t)c*HWD]);
        dfg = fmaf(x, s_f[c], dfg);
        dbg = fmaf(x, s_b[c], dbg);
        nq  = fmaf(x, x, nq);
    }
    int o = s*BB*HWD + b*HWD + p;
    g_p0[o] = dfg; g_p1[o] = dbg; g_p2[o] = nq;
}

// ------------ k2: finalize pred/masks/counts (grid 256) ----------------------
__global__ __launch_bounds__(256)
void k_sim_fin(const float* __restrict__ sfp, const float* __restrict__ sbp,
               const float* __restrict__ tau) {
    __shared__ float sh[32];
    __shared__ int   shc[2][8];
    int b = blockIdx.x >> 4, chunk = blockIdx.x & 15;
    int tid = threadIdx.x;

    float nf = 0.f, nb = 0.f;
    for (int c = tid; c < CC; c += 256) {
        float a = sfp[b*CC + c], d = sbp[b*CC + c];
        nf += a*a; nb += d*d;
    }
    nf = blkSum(nf, sh);
    nb = blkSum(nb, sh);
    float nfp = sqrtf(nf), nbp = sqrtf(nb);
    float ft  = 1.f / (1.f + expf(-tau[0]));
    float bt  = 1.f - ft;

    int p  = (chunk << 8) + tid;
    int gp = b*HWD + p;
    float dfg = 0.f, dbg = 0.f, nq = 0.f;
#pragma unroll
    for (int s = 0; s < SPLIT; s++) {
        int o = s*BB*HWD + gp;
        dfg += g_p0[o]; dbg += g_p1[o]; nq += g_p2[o];
    }
    float inv_q = 1.f / fmaxf(sqrtf(nq), EPSV);
    float cfg = dfg * inv_q / fmaxf(nfp, EPSV);
    float cbg = dbg * inv_q / fmaxf(nbp, EPSV);
    float pf  = 1.f / (1.f + expf(10.f * (cbg - cfg)));
    float pb  = 1.f / (1.f + expf(10.f * (cfg - cbg)));
    bool mfb = pf > ft;
    bool mbb = pb > bt;
    g_pred[gp] = pf;
    g_invq[gp] = inv_q;
    g_mf[gp] = mfb ? 1.f : 0.f;
    g_mb[gp] = mbb ? 1.f : 0.f;

    unsigned bf  = __ballot_sync(0xffffffffu, mfb);
    unsigned bbt = __ballot_sync(0xffffffffu, mbb);
    int w = tid >> 5;
    if ((tid & 31) == 0) { shc[0][w] = __popc(bf); shc[1][w] = __popc(bbt); }
    __syncthreads();
    if (tid == 0) {
        int cf = 0, cb = 0;
#pragma unroll
        for (int j = 0; j < 8; j++) { cf += shc[0][j]; cb += shc[1][j]; }
        atomicAdd(&g_cnt[b],      cf);
        atomicAdd(&g_cnt[BB + b], cb);
    }
}

// ------------ k3: masked channel sums (warp-per-channel, grid 1024) ----------
__global__ __launch_bounds__(256)
void k_msum(const float* __restrict__ feat) {
    __shared__ float4 s_mf4[HWD/4];   // 16 KB
    __shared__ float4 s_mb4[HWD/4];   // 16 KB
    int b = blockIdx.x >> 6, cgrp = blockIdx.x & 63;
    int tid = threadIdx.x, w = tid >> 5, l = tid & 31;

    const float4* mf4 = (const float4*)(g_mf + b*HWD);
    const float4* mb4 = (const float4*)(g_mb + b*HWD);
#pragma unroll
    for (int k = 0; k < 4; k++) {
        s_mf4[tid + k*256] = mf4[tid + k*256];
        s_mb4[tid + k*256] = mb4[tid + k*256];
    }
    __syncthreads();

    int c = (cgrp << 3) + w;
    const float4* row = (const float4*)(feat + ((size_t)(b*CC + c))*HWD);
    float sf = 0.f, sb = 0.f;
#pragma unroll 8
    for (int i = 0; i < 32; i++) {
        int idx = l + (i << 5);
        float4 x = __ldg(&row[idx]);
        float4 mfv = s_mf4[idx];
        float4 mbv = s_mb4[idx];
        sf = fmaf(x.x, mfv.x, sf); sf = fmaf(x.y, mfv.y, sf);
        sf = fmaf(x.z, mfv.z, sf); sf = fmaf(x.w, mfv.w, sf);
        sb = fmaf(x.x, mbv.x, sb); sb = fmaf(x.y, mbv.y, sb);
        sb = fmaf(x.z, mbv.z, sb); sb = fmaf(x.w, mbv.w, sb);
    }
#pragma unroll
    for (int o = 16; o; o >>= 1) {
        sf += __shfl_down_sync(0xffffffffu, sf, o);
        sb += __shfl_down_sync(0xffffffffu, sb, o);
    }
    if (l == 0) { g_fgsum[b*CC + c] = sf; g_bgsum[b*CC + c] = sb; }
}

// ------------ k4: prototypes --------------------------------------------------
__global__ __launch_bounds__(256)
void k_proto(const float* __restrict__ feat, float* __restrict__ outp) {
    __shared__ float sv[HWD];
    __shared__ int   sel[KTOP];
    __shared__ float shf[32];
    __shared__ float rv[8];
    __shared__ int   ri[8];
    int b = blockIdx.x >> 1, cls = blockIdx.x & 1;
    int tid = threadIdx.x;
    int cnt = g_cnt[cls*BB + b];

    if (cnt == 0) {   // stable top-12 fallback
        for (int p = tid; p < HWD; p += 256) {
            float pf = g_pred[b*HWD + p];
            sv[p] = cls ? (1.f - pf) : pf;
        }
        __syncthreads();
        for (int r = 0; r < KTOP; r++) {
            float bv = -1e30f; int bi = HWD;
            for (int p = tid; p < HWD; p += 256) {
                float v = sv[p];
                if (v > bv) { bv = v; bi = p; }
            }
            int lane = tid & 31, w = tid >> 5;
#pragma unroll
            for (int o = 16; o; o >>= 1) {
                float ov = __shfl_down_sync(0xffffffffu, bv, o);
                int   oi = __shfl_down_sync(0xffffffffu, bi, o);
                if (ov > bv || (ov == bv && oi < bi)) { bv = ov; bi = oi; }
            }
            if (lane == 0) { rv[w] = bv; ri[w] = bi; }
            __syncthreads();
            if (tid == 0) {
                for (int j = 1; j < 8; j++)
                    if (rv[j] > bv || (rv[j] == bv && ri[j] < bi)) { bv = rv[j]; bi = ri[j]; }
                sel[r] = bi;
                sv[bi] = -1e30f;
            }
            __syncthreads();
        }
    }
    __syncthreads();

    float inv = (cnt > 0) ? 1.f / (float)cnt : (1.f / (float)KTOP);
    const float* sums = cls ? g_bgsum : g_fgsum;
    float n2 = 0.f;
    for (int c = tid; c < CC; c += 256) {
        float v;
        if (cnt > 0) {
            v = sums[b*CC + c] * inv;
        } else {
            float s = 0.f;
#pragma unroll
            for (int j = 0; j < KTOP; j++)
                s += feat[((size_t)(b*CC + c))*HWD + sel[j]];
            v = s * inv;
        }
        g_proto[(cls*BB + b)*CC + c] = v;
        outp[BIG + cls*BB*CC + b*CC + c] = v;
        n2 += v*v;
    }
    n2 = blkSum(n2, shf);
    if (tid == 0) g_pnorm[cls*BB + b] = sqrtf(n2);
}

// ------------ k5: partial dots vs query protos (split-C, grid 1024) ----------
__global__ __launch_bounds__(256)
void k_act_part(const float* __restrict__ feat) {
    __shared__ float s_f[CPS], s_b[CPS];
    int b = blockIdx.x >> 6, rest = blockIdx.x & 63;
    int s = rest >> 4, chunk = rest & 15;
    int tid = threadIdx.x;

    if (tid < CPS) {
        s_f[tid] = g_proto[b*CC + s*CPS + tid];
        s_b[tid] = g_proto[(BB + b)*CC + s*CPS + tid];
    }
    __syncthreads();

    int p = (chunk << 8) + tid;
    const float* fb = feat + ((size_t)(b*CC + s*CPS))*HWD + p;
    float dfg = 0.f, dbg = 0.f;
#pragma unroll 16
    for (int c = 0; c < CPS; c++) {
        float x = __ldg(&fb[(size_t)c*HWD]);
        dfg = fmaf(x, s_f[c], dfg);
        dbg = fmaf(x, s_b[c], dbg);
    }
    int o = s*BB*HWD + b*HWD + p;
    g_p0[o] = dfg; g_p1[o] = dbg;
}

// ------------ k6: finalize act/deact + minmax (grid 256) ---------------------
__global__ __launch_bounds__(256)
void k_act_fin() {
    __shared__ unsigned shu[32];
    int b = blockIdx.x >> 4, chunk = blockIdx.x & 15;
    int tid = threadIdx.x;
    int p  = (chunk << 8) + tid;
    int gp = b*HWD + p;

    float dfg = 0.f, dbg = 0.f;
#pragma unroll
    for (int s = 0; s < SPLIT; s++) {
        int o = s*BB*HWD + gp;
        dfg += g_p0[o]; dbg += g_p1[o];
    }
    float inv_q = g_invq[gp];
    float nfp = g_pnorm[b], nbp = g_pnorm[BB + b];
    float ca = dfg * inv_q / fmaxf(nfp, EPSV);
    float cd = dbg * inv_q / fmaxf(nbp, EPSV);
    g_act[gp]   = ca;
    g_deact[gp] = cd;

    unsigned amn = blkUMin(fenc(ca), shu);
    unsigned amx = blkUMax(fenc(ca), shu);
    unsigned dmn = blkUMin(fenc(cd), shu);
    unsigned dmx = blkUMax(fenc(cd), shu);
    if (tid == 0) {
        atomicMin(&g_mm[0], amn);
        atomicMax(&g_mm[1], amx);
        atomicMin(&g_mm[2], dmn);
        atomicMax(&g_mm[3], dmx);
    }
}

// ------------ k7: blend output ------------------------------------------------
__global__ __launch_bounds__(256)
void k_out(const float* __restrict__ feat, float* __restrict__ outp) {
    __shared__ float mm[4];
    if (threadIdx.x < 4) mm[threadIdx.x] = fdec(g_mm[threadIdx.x]);
    __syncthreads();
    float amin = mm[0], ira = 1.f / (mm[1] - mm[0]);
    float dmin = mm[2], ird = 1.f / (mm[3] - mm[2]);

    size_t i4 = (size_t)blockIdx.x * 256 + threadIdx.x;
    size_t e  = i4 << 2;
    int b = (int)(e >> 21);
    int p = (int)(e & (HWD - 1));
    float4 x = __ldg(&((const float4*)feat)[i4]);
    int ai = (b*HWD + p) >> 2;
    float4 a = ((const float4*)g_act)[ai];
    float4 d = ((const float4*)g_deact)[ai];
    float4 o;
    o.x = x.x * ((a.x - amin)*ira + 1.f - (d.x - dmin)*ird);
    o.y = x.y * ((a.y - amin)*ira + 1.f - (d.y - dmin)*ird);
    o.z = x.z * ((a.z - amin)*ira + 1.f - (d.z - dmin)*ird);
    o.w = x.w * ((a.w - amin)*ira + 1.f - (d.w - dmin)*ird);
    ((float4*)outp)[i4] = o;
}

// ---------------- launch -----------------------------------------------------
extern "C" void kernel_launch(void* const* d_in, const int* in_sizes, int n_in,
                              void* d_out, int out_size) {
    const float* sfp  = (const float*)d_in[0];
    const float* sbp  = (const float*)d_in[1];
    const float* feat = (const float*)d_in[2];
    const float* tau  = (const float*)d_in[3];
    float* outp = (float*)d_out;

    k_sim_part<<<BB*16*SPLIT, 256>>>(feat, sfp, sbp);
    k_sim_fin <<<BB*16, 256>>>(sfp, sbp, tau);
    k_msum    <<<BB*64, 256>>>(feat);
    k_proto   <<<2*BB, 256>>>(feat, outp);
    k_act_part<<<BB*16*SPLIT, 256>>>(feat);
    k_act_fin <<<BB*16, 256>>>();
    k_out     <<<BIG/4/256, 256>>>(feat, outp);
    (void)in_sizes; (void)n_in; (void)out_size;
}